// round 1
// baseline (speedup 1.0000x reference)
#include <cuda_runtime.h>
#include <cuda_bf16.h>
#include <math.h>

#define T_LEN 512
#define B_SZ  128
#define D_IN  256
#define U_SZ  256
#define NG    768            // 3*U
#define GRID_SCAN 128        // 32 col-groups x 4 batch-groups (<= 148 SMs, spin-safe)
#define WHS 260              // padded column stride (bank-conflict-free, 16B aligned)
#define HSS 260              // padded h row stride

// ---------------- scratch (device globals: allocation-free rule) ----------------
__device__ float    g_x [T_LEN * B_SZ * U_SZ];   // layer input/output, time-major [t][b][256]  (67 MB)
__device__ float    g_xp[T_LEN * B_SZ * NG];     // input projections [t][b][768]              (201 MB)
__device__ float    g_h [2][B_SZ * U_SZ];        // double-buffered hidden state
__device__ unsigned g_bar[T_LEN];                // per-step arrival counters (memset each layer)

// ---------------- embedding gather: x[t][b][:] = emb[tokens[b][t]] ----------------
__global__ void embed_kernel(const int* __restrict__ tokens, const float* __restrict__ emb) {
    int gid = blockIdx.x * blockDim.x + threadIdx.x;   // over T*B*64 float4
    int row = gid >> 6;              // t*B + b
    int c4  = gid & 63;
    int t = row >> 7;                // / 128
    int b = row & 127;
    int tok = tokens[b * T_LEN + t];
    const float4* e4 = reinterpret_cast<const float4*>(emb);
    float4*       x4 = reinterpret_cast<float4*>(g_x);
    x4[(size_t)row * 64 + c4] = e4[(size_t)tok * 64 + c4];
}

// ---------------- input projection GEMM: g_xp = g_x @ W + bias ----------------
// X: [65536, 256] row-major, W: [256, 768] row-major. 128x128 tile, BK=16, 8x8 microtile.
__global__ __launch_bounds__(256) void proj_kernel(const float* __restrict__ W,
                                                   const float* __restrict__ bias) {
    __shared__ float As[16][128];
    __shared__ float Bs[16][128];
    int m0 = blockIdx.x * 128;
    int n0 = blockIdx.y * 128;
    int tid = threadIdx.x;
    int tx = tid & 15, ty = tid >> 4;
    float acc[8][8] = {};

    for (int k0 = 0; k0 < 256; k0 += 16) {
        #pragma unroll
        for (int i = 0; i < 2; i++) {               // A tile: 512 float4, transposed store
            int fid = tid + i * 256;
            int m   = fid >> 2;
            int kv  = fid & 3;
            float4 v = *reinterpret_cast<const float4*>(
                &g_x[(size_t)(m0 + m) * 256 + k0 + kv * 4]);
            As[kv * 4 + 0][m] = v.x; As[kv * 4 + 1][m] = v.y;
            As[kv * 4 + 2][m] = v.z; As[kv * 4 + 3][m] = v.w;
        }
        #pragma unroll
        for (int i = 0; i < 2; i++) {               // B tile: direct copy
            int fid = tid + i * 256;
            int kr  = fid >> 5;
            int nc  = fid & 31;
            *reinterpret_cast<float4*>(&Bs[kr][nc * 4]) =
                *reinterpret_cast<const float4*>(&W[(size_t)(k0 + kr) * NG + n0 + nc * 4]);
        }
        __syncthreads();
        #pragma unroll
        for (int kk = 0; kk < 16; kk++) {
            float a[8], bf[8];
            #pragma unroll
            for (int i = 0; i < 8; i++) a[i]  = As[kk][ty * 8 + i];
            #pragma unroll
            for (int j = 0; j < 8; j++) bf[j] = Bs[kk][tx * 8 + j];
            #pragma unroll
            for (int i = 0; i < 8; i++)
                #pragma unroll
                for (int j = 0; j < 8; j++)
                    acc[i][j] = fmaf(a[i], bf[j], acc[i][j]);
        }
        __syncthreads();
    }
    #pragma unroll
    for (int i = 0; i < 8; i++) {
        size_t m = (size_t)(m0 + ty * 8 + i);
        #pragma unroll
        for (int jv = 0; jv < 2; jv++) {
            float4 o;
            int n = n0 + tx * 8 + jv * 4;
            o.x = acc[i][jv*4+0] + bias[n+0];
            o.y = acc[i][jv*4+1] + bias[n+1];
            o.z = acc[i][jv*4+2] + bias[n+2];
            o.w = acc[i][jv*4+3] + bias[n+3];
            *reinterpret_cast<float4*>(&g_xp[m * NG + n]) = o;
        }
    }
}

// ---------------- recurrent scan: persistent CTAs, per-step chip barrier ----------------
// grid (32, 4): blockIdx.x = column-group (8 hidden units), blockIdx.y = batch-group (32 rows).
// Wh slice (24 cols x 256) lives in SMEM for the whole layer. h exchanged through L2.
extern __shared__ float smem[];
__global__ __launch_bounds__(256) void scan_kernel(const float* __restrict__ Wh,
                                                   const float* __restrict__ bh) {
    float* Wh_s = smem;               // [24 cols][WHS] col = gate*8 + j
    float* h_s  = smem + 24 * WHS;    // [32 rows][HSS]
    int cg = blockIdx.x;              // 0..31
    int bg = blockIdx.y;              // 0..3
    int tid = threadIdx.x;
    int tx = tid & 7;                 // local hidden unit j
    int ty = tid >> 3;                // local batch row 0..31
    int u0 = cg * 8;
    int b0 = bg * 32;

    // one-time Wh slice load (columns u, 256+u, 512+u for u in [u0, u0+8))
    for (int idx = tid; idx < 24 * 256; idx += 256) {
        int col  = idx >> 8;          // 0..23
        int k    = idx & 255;
        int gate = col >> 3;
        int j    = col & 7;
        Wh_s[col * WHS + k] = Wh[(size_t)k * NG + gate * 256 + u0 + j];
    }
    float bhz = bh[0 * 256 + u0 + tx];
    float bhr = bh[1 * 256 + u0 + tx];
    float bhh = bh[2 * 256 + u0 + tx];
    const float4* wz4 = reinterpret_cast<const float4*>(&Wh_s[(0 * 8 + tx) * WHS]);
    const float4* wr4 = reinterpret_cast<const float4*>(&Wh_s[(1 * 8 + tx) * WHS]);
    const float4* wh4 = reinterpret_cast<const float4*>(&Wh_s[(2 * 8 + tx) * WHS]);
    __syncthreads();

    for (int t = 0; t < T_LEN; t++) {
        int par = t & 1;
        // pull this batch-group's 32 h rows from L2 (written by all col-groups last step)
        const float4* hg = reinterpret_cast<const float4*>(&g_h[par][b0 * 256]);
        for (int i = tid; i < 2048; i += 256) {
            float4 v = __ldcg(&hg[i]);
            int row = i >> 6, c = i & 63;
            *reinterpret_cast<float4*>(&h_s[row * HSS + c * 4]) = v;
        }
        __syncthreads();

        const float4* hrow = reinterpret_cast<const float4*>(&h_s[ty * HSS]);
        float az = bhz, ar = bhr, ah = bhh;
        #pragma unroll 8
        for (int k4 = 0; k4 < 64; k4++) {
            float4 hv = hrow[k4];
            float4 az4 = wz4[k4], ar4 = wr4[k4], ah4 = wh4[k4];
            az = fmaf(hv.x, az4.x, az); az = fmaf(hv.y, az4.y, az);
            az = fmaf(hv.z, az4.z, az); az = fmaf(hv.w, az4.w, az);
            ar = fmaf(hv.x, ar4.x, ar); ar = fmaf(hv.y, ar4.y, ar);
            ar = fmaf(hv.z, ar4.z, ar); ar = fmaf(hv.w, ar4.w, ar);
            ah = fmaf(hv.x, ah4.x, ah); ah = fmaf(hv.y, ah4.y, ah);
            ah = fmaf(hv.z, ah4.z, ah); ah = fmaf(hv.w, ah4.w, ah);
        }

        int bglob = b0 + ty;
        int u = u0 + tx;
        size_t xb = ((size_t)t * B_SZ + bglob) * NG;
        float xz = g_xp[xb + u];
        float xr = g_xp[xb + 256 + u];
        float xh = g_xp[xb + 512 + u];
        float z  = 1.f / (1.f + expf(-(xz + az)));
        float r  = 1.f / (1.f + expf(-(xr + ar)));
        float hh = tanhf(xh + r * ah);
        float hold = h_s[ty * HSS + u];
        float hn = z * hold + (1.f - z) * hh;

        __stcg(&g_h[par ^ 1][bglob * 256 + u], hn);
        g_x[((size_t)t * B_SZ + bglob) * 256 + u] = hn;   // next layer's input

        // ---- chip barrier (release: fence-all + bar, arrive+spin by tid0) ----
        __threadfence();
        __syncthreads();
        if (t < T_LEN - 1) {
            if (tid == 0) {
                atomicAdd(&g_bar[t], 1u);
                while (*((volatile unsigned*)&g_bar[t]) < GRID_SCAN) { }
                __threadfence();
            }
            __syncthreads();
        }
    }
}

// ---------------- classifier head ----------------
__global__ void dense_kernel(const float* __restrict__ Wd1, const float* __restrict__ bd1,
                             const float* __restrict__ Wd2, const float* __restrict__ bd2,
                             float* __restrict__ out) {
    __shared__ float xs[256];
    __shared__ float red[256];
    int b = blockIdx.x;
    int j = threadIdx.x;
    xs[j] = g_x[((size_t)(T_LEN - 1) * B_SZ + b) * 256 + j];
    __syncthreads();
    float acc = bd1[j];
    #pragma unroll 8
    for (int k = 0; k < 256; k++) acc = fmaf(xs[k], Wd1[k * 256 + j], acc);
    float h1 = acc > 0.f ? acc : 0.f;
    red[j] = h1 * Wd2[j];
    __syncthreads();
    for (int s = 128; s > 0; s >>= 1) {
        if (j < s) red[j] += red[j + s];
        __syncthreads();
    }
    if (j == 0) out[b] = 1.f / (1.f + expf(-(red[0] + bd2[0])));
}

// ---------------- launch ----------------
extern "C" void kernel_launch(void* const* d_in, const int* in_sizes, int n_in,
                              void* d_out, int out_size) {
    const int*   tokens = (const int*)  d_in[0];
    const float* emb    = (const float*)d_in[1];
    float* out = (float*)d_out;

    void* h_addr;   cudaGetSymbolAddress(&h_addr,   g_h);
    void* bar_addr; cudaGetSymbolAddress(&bar_addr, g_bar);

    const int scan_smem = (24 * WHS + 32 * HSS) * (int)sizeof(float);  // 58560 B
    cudaFuncSetAttribute(scan_kernel, cudaFuncAttributeMaxDynamicSharedMemorySize, scan_smem);

    embed_kernel<<<16384, 256>>>(tokens, emb);

    for (int l = 0; l < 4; l++) {
        const float* Wx = (const float*)d_in[2 + 4 * l];
        const float* Wh = (const float*)d_in[3 + 4 * l];
        const float* bx = (const float*)d_in[4 + 4 * l];
        const float* bh = (const float*)d_in[5 + 4 * l];

        dim3 pgrid(512, 6);
        proj_kernel<<<pgrid, 256>>>(Wx, bx);

        cudaMemsetAsync(h_addr,   0, sizeof(float) * 2 * B_SZ * U_SZ);
        cudaMemsetAsync(bar_addr, 0, sizeof(unsigned) * T_LEN);

        dim3 sgrid(32, 4);
        scan_kernel<<<sgrid, 256, scan_smem>>>(Wh, bh);
    }

    dense_kernel<<<128, 256>>>((const float*)d_in[18], (const float*)d_in[19],
                               (const float*)d_in[20], (const float*)d_in[21], out);
}

// round 2
// speedup vs baseline: 1.2093x; 1.2093x over previous
#include <cuda_runtime.h>
#include <cuda_bf16.h>
#include <math.h>

#define T_LEN 512
#define B_SZ  128
#define D_IN  256
#define U_SZ  256
#define NG    768            // 3*U
#define GRID_SCAN 128        // 32 col-groups x 4 batch-groups (<= 148 SMs, spin-safe)
#define WHS 260              // padded column stride (bank-conflict-free, 16B aligned)
#define HSS 260              // padded h row stride

// ---------------- scratch (device globals: allocation-free rule) ----------------
__device__ float    g_x [T_LEN * B_SZ * U_SZ];   // layer input/output, time-major [t][b][256]
__device__ float    g_xp[T_LEN * B_SZ * NG];     // input projections [t][b][768]
__device__ float    g_h [2][B_SZ * U_SZ];        // double-buffered hidden state
__device__ unsigned g_bar[4 * T_LEN];            // per-(layer,step) arrival counters

// ---------------- embedding gather: x[t][b][:] = emb[tokens[b][t]] ----------------
__global__ void embed_kernel(const int* __restrict__ tokens, const float* __restrict__ emb) {
    int gid = blockIdx.x * blockDim.x + threadIdx.x;   // over T*B*64 float4
    int row = gid >> 6;              // t*B + b
    int c4  = gid & 63;
    int t = row >> 7;                // / 128
    int b = row & 127;
    int tok = tokens[b * T_LEN + t];
    const float4* e4 = reinterpret_cast<const float4*>(emb);
    float4*       x4 = reinterpret_cast<float4*>(g_x);
    x4[(size_t)row * 64 + c4] = e4[(size_t)tok * 64 + c4];
}

// ---------------- input projection GEMM: g_xp = g_x @ W + bias ----------------
__global__ __launch_bounds__(256) void proj_kernel(const float* __restrict__ W,
                                                   const float* __restrict__ bias) {
    __shared__ float As[16][128];
    __shared__ float Bs[16][128];
    int m0 = blockIdx.x * 128;
    int n0 = blockIdx.y * 128;
    int tid = threadIdx.x;
    int tx = tid & 15, ty = tid >> 4;
    float acc[8][8] = {};

    for (int k0 = 0; k0 < 256; k0 += 16) {
        #pragma unroll
        for (int i = 0; i < 2; i++) {               // A tile: transposed store
            int fid = tid + i * 256;
            int m   = fid >> 2;
            int kv  = fid & 3;
            float4 v = *reinterpret_cast<const float4*>(
                &g_x[(size_t)(m0 + m) * 256 + k0 + kv * 4]);
            As[kv * 4 + 0][m] = v.x; As[kv * 4 + 1][m] = v.y;
            As[kv * 4 + 2][m] = v.z; As[kv * 4 + 3][m] = v.w;
        }
        #pragma unroll
        for (int i = 0; i < 2; i++) {               // B tile: direct copy
            int fid = tid + i * 256;
            int kr  = fid >> 5;
            int nc  = fid & 31;
            *reinterpret_cast<float4*>(&Bs[kr][nc * 4]) =
                *reinterpret_cast<const float4*>(&W[(size_t)(k0 + kr) * NG + n0 + nc * 4]);
        }
        __syncthreads();
        #pragma unroll
        for (int kk = 0; kk < 16; kk++) {
            float a[8], bf[8];
            #pragma unroll
            for (int i = 0; i < 8; i++) a[i]  = As[kk][ty * 8 + i];
            #pragma unroll
            for (int j = 0; j < 8; j++) bf[j] = Bs[kk][tx * 8 + j];
            #pragma unroll
            for (int i = 0; i < 8; i++)
                #pragma unroll
                for (int j = 0; j < 8; j++)
                    acc[i][j] = fmaf(a[i], bf[j], acc[i][j]);
        }
        __syncthreads();
    }
    #pragma unroll
    for (int i = 0; i < 8; i++) {
        size_t m = (size_t)(m0 + ty * 8 + i);
        #pragma unroll
        for (int jv = 0; jv < 2; jv++) {
            float4 o;
            int n = n0 + tx * 8 + jv * 4;
            o.x = acc[i][jv*4+0] + bias[n+0];
            o.y = acc[i][jv*4+1] + bias[n+1];
            o.z = acc[i][jv*4+2] + bias[n+2];
            o.w = acc[i][jv*4+3] + bias[n+3];
            *reinterpret_cast<float4*>(&g_xp[m * NG + n]) = o;
        }
    }
}

// ---------------- recurrent scan: persistent CTAs, per-step chip barrier ----------------
// grid (32, 4): blockIdx.x = column-group (8 hidden units), blockIdx.y = batch-group (32 rows).
// Wh slice (24 cols x 256) lives in SMEM for the whole layer. h exchanged through L2.
// Per-step sync: syncthreads -> tid0 red.release + ld.acquire spin -> syncthreads (CG pattern).
extern __shared__ float smem[];
__global__ __launch_bounds__(256) void scan_kernel(const float* __restrict__ Wh,
                                                   const float* __restrict__ bh,
                                                   int layer) {
    float* Wh_s = smem;               // [24 cols][WHS] col = gate*8 + j
    float* h_s  = smem + 24 * WHS;    // [32 rows][HSS]
    int cg = blockIdx.x;              // 0..31
    int bg = blockIdx.y;              // 0..3
    int tid = threadIdx.x;
    int tx = tid & 7;                 // local hidden unit j
    int ty = tid >> 3;                // local batch row 0..31
    int u0 = cg * 8;
    int b0 = bg * 32;
    unsigned* bar = g_bar + layer * T_LEN;

    // one-time Wh slice load (columns u, 256+u, 512+u for u in [u0, u0+8))
    for (int idx = tid; idx < 24 * 256; idx += 256) {
        int col  = idx >> 8;          // 0..23
        int k    = idx & 255;
        int gate = col >> 3;
        int j    = col & 7;
        Wh_s[col * WHS + k] = Wh[(size_t)k * NG + gate * 256 + u0 + j];
    }
    // zero h_s for t=0 (no global h exchange needed at t=0)
    for (int i = tid; i < 32 * HSS; i += 256) h_s[i] = 0.f;

    float bhz = bh[0 * 256 + u0 + tx];
    float bhr = bh[1 * 256 + u0 + tx];
    float bhh = bh[2 * 256 + u0 + tx];
    const float4* wz4 = reinterpret_cast<const float4*>(&Wh_s[(0 * 8 + tx) * WHS]);
    const float4* wr4 = reinterpret_cast<const float4*>(&Wh_s[(1 * 8 + tx) * WHS]);
    const float4* wh4 = reinterpret_cast<const float4*>(&Wh_s[(2 * 8 + tx) * WHS]);

    int bglob = b0 + ty;
    int u = u0 + tx;

    // prologue: xp for t=0 (streaming loads, keep L2 for h-exchange)
    size_t xb0 = (size_t)bglob * NG;
    float xz = __ldcs(&g_xp[xb0 + u]);
    float xr = __ldcs(&g_xp[xb0 + 256 + u]);
    float xh = __ldcs(&g_xp[xb0 + 512 + u]);
    __syncthreads();

    for (int t = 0; t < T_LEN; t++) {
        // prefetch xp(t+1) — hides DRAM latency under the FMA loop
        float nxz = 0.f, nxr = 0.f, nxh = 0.f;
        if (t + 1 < T_LEN) {
            size_t xb = ((size_t)(t + 1) * B_SZ + bglob) * NG;
            nxz = __ldcs(&g_xp[xb + u]);
            nxr = __ldcs(&g_xp[xb + 256 + u]);
            nxh = __ldcs(&g_xp[xb + 512 + u]);
        }

        const float4* hrow = reinterpret_cast<const float4*>(&h_s[ty * HSS]);
        float az = bhz, ar = bhr, ah = bhh;
        #pragma unroll 8
        for (int k4 = 0; k4 < 64; k4++) {
            float4 hv = hrow[k4];
            float4 az4 = wz4[k4], ar4 = wr4[k4], ah4 = wh4[k4];
            az = fmaf(hv.x, az4.x, az); az = fmaf(hv.y, az4.y, az);
            az = fmaf(hv.z, az4.z, az); az = fmaf(hv.w, az4.w, az);
            ar = fmaf(hv.x, ar4.x, ar); ar = fmaf(hv.y, ar4.y, ar);
            ar = fmaf(hv.z, ar4.z, ar); ar = fmaf(hv.w, ar4.w, ar);
            ah = fmaf(hv.x, ah4.x, ah); ah = fmaf(hv.y, ah4.y, ah);
            ah = fmaf(hv.z, ah4.z, ah); ah = fmaf(hv.w, ah4.w, ah);
        }

        float hold = h_s[ty * HSS + u];
        float z  = __fdividef(1.f, 1.f + __expf(-(xz + az)));
        float r  = __fdividef(1.f, 1.f + __expf(-(xr + ar)));
        float hh = tanhf(xh + r * ah);
        float hn = z * hold + (1.f - z) * hh;

        int wbuf = (t & 1) ^ 1;
        __stcg(&g_h[wbuf][bglob * 256 + u], hn);
        g_x[((size_t)t * B_SZ + bglob) * 256 + u] = hn;   // next layer's input

        __syncthreads();   // all h_s reads done + all stcg issued (CTA-scope hb to tid0)

        if (t < T_LEN - 1) {
            if (tid == 0) {
                unsigned* a = &bar[t];
                asm volatile("red.release.gpu.global.add.u32 [%0], %1;"
                             :: "l"(a), "r"(1u) : "memory");
                unsigned v;
                do {
                    asm volatile("ld.acquire.gpu.global.u32 %0, [%1];"
                                 : "=r"(v) : "l"(a) : "memory");
                } while (v < GRID_SCAN);
            }
            __syncthreads();
            // pull this batch-group's 32 h rows from L2
            const float4* hg = reinterpret_cast<const float4*>(&g_h[wbuf][b0 * 256]);
            for (int i = tid; i < 2048; i += 256) {
                float4 v = __ldcg(&hg[i]);
                int row = i >> 6, c = i & 63;
                *reinterpret_cast<float4*>(&h_s[row * HSS + c * 4]) = v;
            }
            __syncthreads();
        }
        xz = nxz; xr = nxr; xh = nxh;
    }
}

// ---------------- classifier head ----------------
__global__ void dense_kernel(const float* __restrict__ Wd1, const float* __restrict__ bd1,
                             const float* __restrict__ Wd2, const float* __restrict__ bd2,
                             float* __restrict__ out) {
    __shared__ float xs[256];
    __shared__ float red[256];
    int b = blockIdx.x;
    int j = threadIdx.x;
    xs[j] = g_x[((size_t)(T_LEN - 1) * B_SZ + b) * 256 + j];
    __syncthreads();
    float acc = bd1[j];
    #pragma unroll 8
    for (int k = 0; k < 256; k++) acc = fmaf(xs[k], Wd1[k * 256 + j], acc);
    float h1 = acc > 0.f ? acc : 0.f;
    red[j] = h1 * Wd2[j];
    __syncthreads();
    for (int s = 128; s > 0; s >>= 1) {
        if (j < s) red[j] += red[j + s];
        __syncthreads();
    }
    if (j == 0) out[b] = 1.f / (1.f + expf(-(red[0] + bd2[0])));
}

// ---------------- launch ----------------
extern "C" void kernel_launch(void* const* d_in, const int* in_sizes, int n_in,
                              void* d_out, int out_size) {
    const int*   tokens = (const int*)  d_in[0];
    const float* emb    = (const float*)d_in[1];
    float* out = (float*)d_out;

    void* bar_addr; cudaGetSymbolAddress(&bar_addr, g_bar);

    const int scan_smem = (24 * WHS + 32 * HSS) * (int)sizeof(float);  // 58240 B
    cudaFuncSetAttribute(scan_kernel, cudaFuncAttributeMaxDynamicSharedMemorySize, scan_smem);

    // one memset for all 4 layers' barrier counters
    cudaMemsetAsync(bar_addr, 0, sizeof(unsigned) * 4 * T_LEN);

    embed_kernel<<<16384, 256>>>(tokens, emb);

    for (int l = 0; l < 4; l++) {
        const float* Wx = (const float*)d_in[2 + 4 * l];
        const float* Wh = (const float*)d_in[3 + 4 * l];
        const float* bx = (const float*)d_in[4 + 4 * l];
        const float* bh = (const float*)d_in[5 + 4 * l];

        dim3 pgrid(512, 6);
        proj_kernel<<<pgrid, 256>>>(Wx, bx);

        dim3 sgrid(32, 4);
        scan_kernel<<<sgrid, 256, scan_smem>>>(Wh, bh, l);
    }

    dense_kernel<<<128, 256>>>((const float*)d_in[18], (const float*)d_in[19],
                               (const float*)d_in[20], (const float*)d_in[21], out);
}

// round 3
// speedup vs baseline: 1.7725x; 1.4658x over previous
#include <cuda_runtime.h>
#include <cuda_bf16.h>
#include <math.h>

#define T_LEN 512
#define B_SZ  128
#define D_IN  256
#define U_SZ  256
#define NG    768            // 3*U
#define WHS 260              // padded column stride
#define HSS 260              // padded h row stride
#define BG_CTAS 32           // CTAs per batch-group barrier

// ---------------- scratch ----------------
__device__ float    g_x [T_LEN * B_SZ * U_SZ];
__device__ float    g_xp[T_LEN * B_SZ * NG];
__device__ float    g_h [2][B_SZ * U_SZ];
__device__ unsigned g_bar[4 * T_LEN * 4];        // [layer][t][bg]

// ---------------- embedding ----------------
__global__ void embed_kernel(const int* __restrict__ tokens, const float* __restrict__ emb) {
    int gid = blockIdx.x * blockDim.x + threadIdx.x;
    int row = gid >> 6;
    int c4  = gid & 63;
    int t = row >> 7;
    int b = row & 127;
    int tok = tokens[b * T_LEN + t];
    const float4* e4 = reinterpret_cast<const float4*>(emb);
    float4*       x4 = reinterpret_cast<float4*>(g_x);
    x4[(size_t)row * 64 + c4] = e4[(size_t)tok * 64 + c4];
}

// ---------------- input projection GEMM ----------------
__global__ __launch_bounds__(256) void proj_kernel(const float* __restrict__ W,
                                                   const float* __restrict__ bias) {
    __shared__ float As[16][128];
    __shared__ float Bs[16][128];
    int m0 = blockIdx.x * 128;
    int n0 = blockIdx.y * 128;
    int tid = threadIdx.x;
    int tx = tid & 15, ty = tid >> 4;
    float acc[8][8] = {};

    for (int k0 = 0; k0 < 256; k0 += 16) {
        #pragma unroll
        for (int i = 0; i < 2; i++) {
            int fid = tid + i * 256;
            int m   = fid >> 2;
            int kv  = fid & 3;
            float4 v = *reinterpret_cast<const float4*>(
                &g_x[(size_t)(m0 + m) * 256 + k0 + kv * 4]);
            As[kv * 4 + 0][m] = v.x; As[kv * 4 + 1][m] = v.y;
            As[kv * 4 + 2][m] = v.z; As[kv * 4 + 3][m] = v.w;
        }
        #pragma unroll
        for (int i = 0; i < 2; i++) {
            int fid = tid + i * 256;
            int kr  = fid >> 5;
            int nc  = fid & 31;
            *reinterpret_cast<float4*>(&Bs[kr][nc * 4]) =
                *reinterpret_cast<const float4*>(&W[(size_t)(k0 + kr) * NG + n0 + nc * 4]);
        }
        __syncthreads();
        #pragma unroll
        for (int kk = 0; kk < 16; kk++) {
            float a[8], bf[8];
            #pragma unroll
            for (int i = 0; i < 8; i++) a[i]  = As[kk][ty * 8 + i];
            #pragma unroll
            for (int j = 0; j < 8; j++) bf[j] = Bs[kk][tx * 8 + j];
            #pragma unroll
            for (int i = 0; i < 8; i++)
                #pragma unroll
                for (int j = 0; j < 8; j++)
                    acc[i][j] = fmaf(a[i], bf[j], acc[i][j]);
        }
        __syncthreads();
    }
    #pragma unroll
    for (int i = 0; i < 8; i++) {
        size_t m = (size_t)(m0 + ty * 8 + i);
        #pragma unroll
        for (int jv = 0; jv < 2; jv++) {
            float4 o;
            int n = n0 + tx * 8 + jv * 4;
            o.x = acc[i][jv*4+0] + bias[n+0];
            o.y = acc[i][jv*4+1] + bias[n+1];
            o.z = acc[i][jv*4+2] + bias[n+2];
            o.w = acc[i][jv*4+3] + bias[n+3];
            *reinterpret_cast<float4*>(&g_xp[m * NG + n]) = o;
        }
    }
}

// ---------------- recurrent scan ----------------
// grid (32, 4): cg = 8 hidden units, bg = 32 batch rows.
// GEMM phase: 256 threads = 64 positions (8 row-groups x 8 units) x 4 K-slices.
//   Thread tile: 4 rows x 3 gates, K=64. 7 LDS.128 -> 48 FMA per k4.
// Epilogue phase: tid = r*8 + j, K-partials reduced via smem.
extern __shared__ float smem[];
__global__ __launch_bounds__(256) void scan_kernel(const float* __restrict__ Wh,
                                                   const float* __restrict__ bh,
                                                   int layer) {
    float* Wh_s = smem;                       // [24 cols][WHS], col = gate*8 + j
    float* h_s  = smem + 24 * WHS;            // [32 rows][HSS]
    float* red  = smem + 24 * WHS + 32 * HSS; // [4 ks][64 p][12]
    int cg = blockIdx.x;
    int bg = blockIdx.y;
    int tid = threadIdx.x;
    int u0 = cg * 8;
    int b0 = bg * 32;
    unsigned* bar = g_bar + (layer * T_LEN) * 4 + bg;

    // GEMM-phase decode
    int ks  = tid >> 6;            // 0..3  K-slice
    int pos = tid & 63;            // 0..63
    int ty2 = pos >> 3;            // row-group 0..7 (rows ty2*4..+3)
    int txg = pos & 7;             // unit 0..7

    // Epilogue decode
    int er = tid >> 3;             // row 0..31
    int ej = tid & 7;              // unit 0..7
    int ep = (er >> 2) * 8 + ej;   // position owning (er, ej)
    int erp = er & 3;              // row-in-position

    // one-time Wh slice load
    for (int idx = tid; idx < 24 * 256; idx += 256) {
        int col  = idx >> 8;
        int k    = idx & 255;
        int gate = col >> 3;
        int j    = col & 7;
        Wh_s[col * WHS + k] = Wh[(size_t)k * NG + gate * 256 + u0 + j];
    }
    for (int i = tid; i < 32 * HSS; i += 256) h_s[i] = 0.f;

    float bhz = bh[0 * 256 + u0 + ej];
    float bhr = bh[1 * 256 + u0 + ej];
    float bhh = bh[2 * 256 + u0 + ej];

    const float4* wz4 = reinterpret_cast<const float4*>(&Wh_s[(0 * 8 + txg) * WHS + ks * 64]);
    const float4* wr4 = reinterpret_cast<const float4*>(&Wh_s[(1 * 8 + txg) * WHS + ks * 64]);
    const float4* wh4 = reinterpret_cast<const float4*>(&Wh_s[(2 * 8 + txg) * WHS + ks * 64]);
    const float4* h0_4 = reinterpret_cast<const float4*>(&h_s[(ty2 * 4 + 0) * HSS + ks * 64]);
    const float4* h1_4 = reinterpret_cast<const float4*>(&h_s[(ty2 * 4 + 1) * HSS + ks * 64]);
    const float4* h2_4 = reinterpret_cast<const float4*>(&h_s[(ty2 * 4 + 2) * HSS + ks * 64]);
    const float4* h3_4 = reinterpret_cast<const float4*>(&h_s[(ty2 * 4 + 3) * HSS + ks * 64]);
    float* myred = &red[(ks * 64 + pos) * 12];

    int bglob = b0 + er;
    int u = u0 + ej;

    // prologue: xp(t=0)
    size_t xb0 = (size_t)bglob * NG;
    float xz = __ldcs(&g_xp[xb0 + u]);
    float xr = __ldcs(&g_xp[xb0 + 256 + u]);
    float xh = __ldcs(&g_xp[xb0 + 512 + u]);
    __syncthreads();

    for (int t = 0; t < T_LEN; t++) {
        // prefetch xp(t+1)
        float nxz = 0.f, nxr = 0.f, nxh = 0.f;
        if (t + 1 < T_LEN) {
            size_t xb = ((size_t)(t + 1) * B_SZ + bglob) * NG;
            nxz = __ldcs(&g_xp[xb + u]);
            nxr = __ldcs(&g_xp[xb + 256 + u]);
            nxh = __ldcs(&g_xp[xb + 512 + u]);
        }

        // ---- GEMM phase: acc[4 rows][3 gates] over K-slice of 64 ----
        float az0=0,az1=0,az2=0,az3=0, ar0=0,ar1=0,ar2=0,ar3=0, ah0=0,ah1=0,ah2=0,ah3=0;
        #pragma unroll 4
        for (int k4 = 0; k4 < 16; k4++) {
            float4 w_z = wz4[k4], w_r = wr4[k4], w_h = wh4[k4];
            float4 v0 = h0_4[k4], v1 = h1_4[k4], v2 = h2_4[k4], v3 = h3_4[k4];
            az0 = fmaf(v0.x,w_z.x,az0); az0 = fmaf(v0.y,w_z.y,az0); az0 = fmaf(v0.z,w_z.z,az0); az0 = fmaf(v0.w,w_z.w,az0);
            az1 = fmaf(v1.x,w_z.x,az1); az1 = fmaf(v1.y,w_z.y,az1); az1 = fmaf(v1.z,w_z.z,az1); az1 = fmaf(v1.w,w_z.w,az1);
            az2 = fmaf(v2.x,w_z.x,az2); az2 = fmaf(v2.y,w_z.y,az2); az2 = fmaf(v2.z,w_z.z,az2); az2 = fmaf(v2.w,w_z.w,az2);
            az3 = fmaf(v3.x,w_z.x,az3); az3 = fmaf(v3.y,w_z.y,az3); az3 = fmaf(v3.z,w_z.z,az3); az3 = fmaf(v3.w,w_z.w,az3);
            ar0 = fmaf(v0.x,w_r.x,ar0); ar0 = fmaf(v0.y,w_r.y,ar0); ar0 = fmaf(v0.z,w_r.z,ar0); ar0 = fmaf(v0.w,w_r.w,ar0);
            ar1 = fmaf(v1.x,w_r.x,ar1); ar1 = fmaf(v1.y,w_r.y,ar1); ar1 = fmaf(v1.z,w_r.z,ar1); ar1 = fmaf(v1.w,w_r.w,ar1);
            ar2 = fmaf(v2.x,w_r.x,ar2); ar2 = fmaf(v2.y,w_r.y,ar2); ar2 = fmaf(v2.z,w_r.z,ar2); ar2 = fmaf(v2.w,w_r.w,ar2);
            ar3 = fmaf(v3.x,w_r.x,ar3); ar3 = fmaf(v3.y,w_r.y,ar3); ar3 = fmaf(v3.z,w_r.z,ar3); ar3 = fmaf(v3.w,w_r.w,ar3);
            ah0 = fmaf(v0.x,w_h.x,ah0); ah0 = fmaf(v0.y,w_h.y,ah0); ah0 = fmaf(v0.z,w_h.z,ah0); ah0 = fmaf(v0.w,w_h.w,ah0);
            ah1 = fmaf(v1.x,w_h.x,ah1); ah1 = fmaf(v1.y,w_h.y,ah1); ah1 = fmaf(v1.z,w_h.z,ah1); ah1 = fmaf(v1.w,w_h.w,ah1);
            ah2 = fmaf(v2.x,w_h.x,ah2); ah2 = fmaf(v2.y,w_h.y,ah2); ah2 = fmaf(v2.z,w_h.z,ah2); ah2 = fmaf(v2.w,w_h.w,ah2);
            ah3 = fmaf(v3.x,w_h.x,ah3); ah3 = fmaf(v3.y,w_h.y,ah3); ah3 = fmaf(v3.z,w_h.z,ah3); ah3 = fmaf(v3.w,w_h.w,ah3);
        }
        // store partials: red[ks][pos][row'*3 + gate]
        {
            float4 s0 = make_float4(az0, ar0, ah0, az1);
            float4 s1 = make_float4(ar1, ah1, az2, ar2);
            float4 s2 = make_float4(ah2, az3, ar3, ah3);
            float4* r4 = reinterpret_cast<float4*>(myred);
            r4[0] = s0; r4[1] = s1; r4[2] = s2;
        }
        __syncthreads();

        // ---- epilogue: thread (er, ej) sums 4 K-partials per gate ----
        float az = bhz, ar = bhr, ah = bhh;
        #pragma unroll
        for (int s = 0; s < 4; s++) {
            const float* rr = &red[(s * 64 + ep) * 12 + erp * 3];
            az += rr[0]; ar += rr[1]; ah += rr[2];
        }

        float hold = h_s[er * HSS + u];
        float z  = __fdividef(1.f, 1.f + __expf(-(xz + az)));
        float r  = __fdividef(1.f, 1.f + __expf(-(xr + ar)));
        float hh = tanhf(xh + r * ah);
        float hn = z * hold + (1.f - z) * hh;

        int wbuf = (t & 1) ^ 1;
        __stcg(&g_h[wbuf][bglob * 256 + u], hn);

        __syncthreads();   // h_s reads done + stcg issued

        if (t < T_LEN - 1) {
            if (tid == 0) {
                g_x[((size_t)t * B_SZ + bglob) * 256 + u] = hn;
                unsigned* a = &bar[t * 4];
                asm volatile("red.release.gpu.global.add.u32 [%0], %1;"
                             :: "l"(a), "r"(1u) : "memory");
                unsigned v;
                do {
                    asm volatile("ld.acquire.gpu.global.u32 %0, [%1];"
                                 : "=r"(v) : "l"(a) : "memory");
                } while (v < BG_CTAS);
            } else {
                g_x[((size_t)t * B_SZ + bglob) * 256 + u] = hn;  // overlap with spin
            }
            __syncthreads();
            // reload h_s from L2
            const float4* hg = reinterpret_cast<const float4*>(&g_h[wbuf][b0 * 256]);
            for (int i = tid; i < 2048; i += 256) {
                float4 v = __ldcg(&hg[i]);
                int row = i >> 6, c = i & 63;
                *reinterpret_cast<float4*>(&h_s[row * HSS + c * 4]) = v;
            }
            __syncthreads();
        } else {
            g_x[((size_t)t * B_SZ + bglob) * 256 + u] = hn;
        }
        xz = nxz; xr = nxr; xh = nxh;
    }
}

// ---------------- classifier head ----------------
__global__ void dense_kernel(const float* __restrict__ Wd1, const float* __restrict__ bd1,
                             const float* __restrict__ Wd2, const float* __restrict__ bd2,
                             float* __restrict__ out) {
    __shared__ float xs[256];
    __shared__ float red[256];
    int b = blockIdx.x;
    int j = threadIdx.x;
    xs[j] = g_x[((size_t)(T_LEN - 1) * B_SZ + b) * 256 + j];
    __syncthreads();
    float acc = bd1[j];
    #pragma unroll 8
    for (int k = 0; k < 256; k++) acc = fmaf(xs[k], Wd1[k * 256 + j], acc);
    float h1 = acc > 0.f ? acc : 0.f;
    red[j] = h1 * Wd2[j];
    __syncthreads();
    for (int s = 128; s > 0; s >>= 1) {
        if (j < s) red[j] += red[j + s];
        __syncthreads();
    }
    if (j == 0) out[b] = 1.f / (1.f + expf(-(red[0] + bd2[0])));
}

// ---------------- launch ----------------
extern "C" void kernel_launch(void* const* d_in, const int* in_sizes, int n_in,
                              void* d_out, int out_size) {
    const int*   tokens = (const int*)  d_in[0];
    const float* emb    = (const float*)d_in[1];
    float* out = (float*)d_out;

    void* bar_addr; cudaGetSymbolAddress(&bar_addr, g_bar);

    const int scan_smem = (24 * WHS + 32 * HSS + 4 * 64 * 12) * (int)sizeof(float); // 70528 B
    cudaFuncSetAttribute(scan_kernel, cudaFuncAttributeMaxDynamicSharedMemorySize, scan_smem);

    cudaMemsetAsync(bar_addr, 0, sizeof(unsigned) * 4 * T_LEN * 4);

    embed_kernel<<<16384, 256>>>(tokens, emb);

    for (int l = 0; l < 4; l++) {
        const float* Wx = (const float*)d_in[2 + 4 * l];
        const float* Wh = (const float*)d_in[3 + 4 * l];
        const float* bx = (const float*)d_in[4 + 4 * l];
        const float* bh = (const float*)d_in[5 + 4 * l];

        dim3 pgrid(512, 6);
        proj_kernel<<<pgrid, 256>>>(Wx, bx);

        dim3 sgrid(32, 4);
        scan_kernel<<<sgrid, 256, scan_smem>>>(Wh, bh, l);
    }

    dense_kernel<<<128, 256>>>((const float*)d_in[18], (const float*)d_in[19],
                               (const float*)d_in[20], (const float*)d_in[21], out);
}